// round 13
// baseline (speedup 1.0000x reference)
#include <cuda_runtime.h>
#include <cuda_bf16.h>
#include <cstdint>

#define BB   8192
#define JJ   16
#define NHID 128
#define NS4  (4*BB)
#define NRMAX (NS4*JJ)              // 524288 rows
#define EPSB 1e-5f
#define INVN (1.0/131072.0)

// smem layout (bytes), 272B padded rows (conflict-free LDSM)
#define ROWP      272
#define ABUF      (64*ROWP)                     // 17408 per (hi or lo) 64-row buffer
#define OFF_A0H   0
#define OFF_A0L   ABUF
#define OFF_A1H   (2*ABUF)
#define OFF_A1L   (3*ABUF)
#define OFF_WH    (4*ABUF)                      // 69632
#define OFF_WL    (OFF_WH + 256*ROWP)
#define GEMM_SMEM (OFF_WL + 256*ROWP)           // 208896

// ---------------- persistent scratch ----------------
__device__ float         g_H  [NRMAX*NHID];
__device__ __nv_bfloat16 g_Xh0[NRMAX*NHID];
__device__ __nv_bfloat16 g_Xl0[NRMAX*NHID];
__device__ __nv_bfloat16 g_Xh1[NRMAX*NHID];
__device__ __nv_bfloat16 g_Xl1[NRMAX*NHID];
__device__ __nv_bfloat16 g_Wbf[8*2*256*128];   // [stage][hi/lo][n=256][k=128]
__device__ float  g_merged[BB*JJ*12];
__device__ float  g_att[15*JJ*JJ];
__device__ double g_sum  [18*4*NHID];          // [slot][set][128]
__device__ double g_sumsq[18*4*NHID];

__constant__ unsigned short c_mask[16] = {
 0x0093,0x0007,0x000E,0x000C,0x0031,0x0070,0x0060,0x0181,
 0x4B80,0x0700,0x0600,0x1900,0x3800,0x3000,0xC100,0xC000};

// ---------------- PTX helpers ----------------
__device__ __forceinline__ uint32_t smem_u32(const void* p) {
    uint32_t a;
    asm("{ .reg .u64 t; cvta.to.shared.u64 t, %1; cvt.u32.u64 %0, t; }" : "=r"(a) : "l"(p));
    return a;
}
__device__ __forceinline__ void mma16816(float* c, const uint32_t* a, const uint32_t* b) {
    asm volatile("mma.sync.aligned.m16n8k16.row.col.f32.bf16.bf16.f32 "
        "{%0,%1,%2,%3}, {%4,%5,%6,%7}, {%8,%9}, {%0,%1,%2,%3};"
        : "+f"(c[0]), "+f"(c[1]), "+f"(c[2]), "+f"(c[3])
        : "r"(a[0]), "r"(a[1]), "r"(a[2]), "r"(a[3]), "r"(b[0]), "r"(b[1]));
}
__device__ __forceinline__ void ldsm4(uint32_t* r, uint32_t addr) {
    asm volatile("ldmatrix.sync.aligned.m8n8.x4.shared.b16 {%0,%1,%2,%3}, [%4];"
        : "=r"(r[0]), "=r"(r[1]), "=r"(r[2]), "=r"(r[3]) : "r"(addr));
}
#define CP_ASYNC16(dst, src) asm volatile("cp.async.cg.shared.global [%0], [%1], 16;" :: "r"(dst), "l"(src))
#define CP_COMMIT()          asm volatile("cp.async.commit_group;")
#define CP_WAIT0()           asm volatile("cp.async.wait_group 0;")

// ---------------- prep: masked softmax + zero stat slots ----------------
__global__ void sg_prep(const float* __restrict__ e_in, const float* __restrict__ e_cat,
                        const float* __restrict__ e_res, const float* __restrict__ e_out)
{
    int t = threadIdx.x;
    for (int i = t; i < 18*4*NHID; i += 256) { g_sum[i] = 0.0; g_sumsq[i] = 0.0; }
    if (t < 240) {
        int slot = t >> 4, i = t & 15;
        const float* e;
        if (slot == 0)      e = e_in;
        else if (slot == 1) e = e_cat;
        else if (slot < 10) e = e_res + (slot-2)*256;
        else                e = e_out + (slot-10)*256;
        unsigned m = c_mask[i];
        float mx = -1e30f;
        for (int j = 0; j < 16; j++) if ((m>>j)&1) mx = fmaxf(mx, e[i*16+j]);
        float v[16]; float s = 0.f;
        for (int j = 0; j < 16; j++) {
            float x = ((m>>j)&1) ? expf(e[i*16+j]-mx) : 0.f;
            v[j] = x; s += x;
        }
        float inv = 1.f/s;
        for (int j = 0; j < 16; j++) g_att[slot*256 + i*16 + j] = v[j]*inv;
    }
}

// ---------------- weight bf16 hi/lo split: g_Wbf[stage][hi/lo][n][k] ----------------
__global__ void sg_wprep(const float* __restrict__ W_res)
{
    int idx = blockIdx.x*256 + threadIdx.x;     // < 262144
    int s = idx >> 15;
    int part = (idx >> 14) & 1;
    int k = (idx >> 7) & 127;
    int c = idx & 127;
    float w = W_res[(((s*2 + part)*128) + k)*128 + c];
    __nv_bfloat16 hi = __float2bfloat16(w);
    __nv_bfloat16 lo = __float2bfloat16(w - __bfloat162float(hi));
    int n = part*128 + c;
    g_Wbf[((long)(s*2+0)*256 + n)*128 + k] = hi;
    g_Wbf[((long)(s*2+1)*256 + n)*128 + k] = lo;
}

// ---------------- small-K input gconv (K=2 / K=12), input-space mixing ----------------
template<int KIN>
__global__ void sg_gconv_smallk(const float* __restrict__ x0, const float* __restrict__ x1,
                                const float* __restrict__ x2, const float* __restrict__ x3,
                                int fourway, const float* __restrict__ W,
                                const float* __restrict__ bias, int attSlot, int slot,
                                float* __restrict__ H)
{
    __shared__ float xs [8][16][KIN];
    __shared__ float y0s[8][16][KIN];
    __shared__ float y1s[8][16][KIN];
    __shared__ float Ws[2*KIN*NHID];
    __shared__ float attS[256];
    int t  = threadIdx.x;              // 128
    int s0 = blockIdx.x * 8;
    int set = blockIdx.x >> 10;

    for (int i = t; i < 2*KIN*NHID; i += 128) Ws[i] = W[i];
    for (int i = t; i < 256; i += 128) attS[i] = g_att[attSlot*256 + i];

    const int total = 8*16*KIN;
    for (int i = t; i < total; i += 128) {
        int s = i/(16*KIN); int rem = i - s*16*KIN; int j = rem/KIN; int k = rem - j*KIN;
        int gs = s0 + s;
        const float* xp; int loc;
        if (fourway) {
            int br = gs >> 13; loc = gs & (BB-1);
            xp = (br==0)?x0:(br==1)?x1:(br==2)?x2:x3;
        } else { xp = x0; loc = gs; }
        xs[s][j][k] = xp[(loc*16 + j)*KIN + k];
    }
    __syncthreads();
    for (int i = t; i < total; i += 128) {
        int s = i/(16*KIN); int rem = i - s*16*KIN; int ji = rem/KIN; int k = rem - ji*KIN;
        float a1 = 0.f;
        #pragma unroll
        for (int j = 0; j < 16; j++) a1 += attS[ji*16+j]*xs[s][j][k];
        a1 -= attS[ji*17]*xs[s][ji][k];
        y0s[s][ji][k] = attS[ji*17]*xs[s][ji][k];
        y1s[s][ji][k] = a1;
    }
    __syncthreads();
    int c = t;
    float w0[KIN], w1[KIN];
    #pragma unroll
    for (int k = 0; k < KIN; k++) { w0[k] = Ws[k*NHID+c]; w1[k] = Ws[(KIN+k)*NHID+c]; }
    float bb = bias[c];
    float bsum = 0.f, bsq = 0.f;
    for (int s = 0; s < 8; s++)
        for (int ji = 0; ji < 16; ji++) {
            float h = bb;
            #pragma unroll
            for (int k = 0; k < KIN; k++) h += y0s[s][ji][k]*w0[k] + y1s[s][ji][k]*w1[k];
            H[((long)(s0+s)*16 + ji)*NHID + c] = h;
            bsum += h; bsq += h*h;
        }
    atomicAdd(&g_sum  [slot*512 + set*128 + c], (double)bsum);
    atomicAdd(&g_sumsq[slot*512 + set*128 + c], (double)bsq);
}

// ---------------- convert: BN(affine from stats) + ReLU (+res) -> bf16 hi/lo --------
__global__ void sg_convert(const float* __restrict__ H,
                           const __nv_bfloat16* __restrict__ Rh, const __nv_bfloat16* __restrict__ Rl,
                           __nv_bfloat16* __restrict__ Xh, __nv_bfloat16* __restrict__ Xl,
                           const float* __restrict__ gma, const float* __restrict__ bta,
                           int slotIn)
{
    int t = threadIdx.x;               // 256
    long base = (long)blockIdx.x * 8192;   // 64 rows
    int set = blockIdx.x >> 11;
    int c0 = (t*4) & 127;
    float a[4], b[4];
    #pragma unroll
    for (int k = 0; k < 4; k++) {
        double s = g_sum  [slotIn*512 + set*128 + c0 + k];
        double q = g_sumsq[slotIn*512 + set*128 + c0 + k];
        float mu  = (float)(s*INVN);
        float var = (float)(q*INVN) - mu*mu;
        float istd = rsqrtf(var + EPSB);
        float gg = gma[c0+k];
        a[k] = istd*gg; b[k] = bta[c0+k] - mu*istd*gg;
    }
    for (int i = t*4; i < 8192; i += 1024) {
        float4 h = *(const float4*)(H + base + i);
        float v[4];
        v[0] = fmaxf(fmaf(h.x, a[0], b[0]), 0.f);
        v[1] = fmaxf(fmaf(h.y, a[1], b[1]), 0.f);
        v[2] = fmaxf(fmaf(h.z, a[2], b[2]), 0.f);
        v[3] = fmaxf(fmaf(h.w, a[3], b[3]), 0.f);
        if (Rh) {
            __nv_bfloat162 rh0 = *(const __nv_bfloat162*)(Rh + base + i);
            __nv_bfloat162 rh1 = *(const __nv_bfloat162*)(Rh + base + i + 2);
            __nv_bfloat162 rl0 = *(const __nv_bfloat162*)(Rl + base + i);
            __nv_bfloat162 rl1 = *(const __nv_bfloat162*)(Rl + base + i + 2);
            v[0] += __bfloat162float(rh0.x) + __bfloat162float(rl0.x);
            v[1] += __bfloat162float(rh0.y) + __bfloat162float(rl0.y);
            v[2] += __bfloat162float(rh1.x) + __bfloat162float(rl1.x);
            v[3] += __bfloat162float(rh1.y) + __bfloat162float(rl1.y);
        }
        __nv_bfloat16 hh[4], ll[4];
        #pragma unroll
        for (int k = 0; k < 4; k++) {
            hh[k] = __float2bfloat16(v[k]);
            ll[k] = __float2bfloat16(v[k] - __bfloat162float(hh[k]));
        }
        __nv_bfloat162 p0, p1, q0, q1;
        p0.x = hh[0]; p0.y = hh[1]; p1.x = hh[2]; p1.y = hh[3];
        q0.x = ll[0]; q0.y = ll[1]; q1.x = ll[2]; q1.y = ll[3];
        *(__nv_bfloat162*)(Xh + base + i)     = p0;
        *(__nv_bfloat162*)(Xh + base + i + 2) = p1;
        *(__nv_bfloat162*)(Xl + base + i)     = q0;
        *(__nv_bfloat162*)(Xl + base + i + 2) = q1;
    }
}

// ---------------- pair gemm: ratio-6 mainloop + chunk-major epilogue ----------------
// 256 threads, 8 warps (2x4), warp tile 64(M)x64(N); wm = chunk within the pair.
// Epilogue is chunk-major: after chunk0's mix its A region is free and chunk0's
// next-pair cp.async is issued immediately, overlapping chunk1's epilogue.
__global__ __launch_bounds__(256) void sg_gemm_pipe(
    const __nv_bfloat16* __restrict__ Xh, const __nv_bfloat16* __restrict__ Xl,
    const __nv_bfloat16* __restrict__ Wbf, const float* __restrict__ bias,
    int attSlot, int slotOut, int tpc, float* __restrict__ Hout)
{
    extern __shared__ char dsm[];
    __shared__ float att2[256];
    __shared__ float dS[16];
    __shared__ float bS[128];
    __shared__ float sSum[128], sSq[128];

    int tid = threadIdx.x, wid = tid >> 5, lane = tid & 31;
    int wm = wid >> 2, wn = wid & 3;   // 2x4 warp grid, warp tile 64(M) x 64(N)
    int chunk0 = blockIdx.x * tpc;
    int set = chunk0 >> 11;            // 2048 chunks per BN set
    int npairs = tpc >> 1;
    uint32_t sbase = smem_u32(dsm);

    // ---- preamble: W (hi+lo) + A pair0 ----
    {
        const char* wsrc = (const char*)Wbf;
        #pragma unroll
        for (int j = 0; j < 32; j++) {
            int idx = tid + j*256;             // 8192 W pieces
            int kind = idx >> 12, rem = idx & 4095;
            int r = rem >> 4, p = rem & 15;
            uint32_t dst = sbase + (kind ? OFF_WL : OFF_WH) + r*ROWP + p*16;
            CP_ASYNC16(dst, wsrc + kind*65536 + r*256 + p*16);
        }
        long rowP = (long)chunk0 * 64;
        #pragma unroll
        for (int j = 0; j < 16; j++) {
            int idx = tid + j*256;             // 4096 A pieces (128 rows x hi/lo)
            int cnk  = idx >> 11;
            int kind = (idx >> 10) & 1;
            int rem  = idx & 1023;
            int r = rem >> 4, p = rem & 15;
            const char* src = (const char*)(kind ? Xl : Xh) + (rowP + cnk*64 + r)*256 + p*16;
            uint32_t dst = sbase + (cnk ? OFF_A1H : OFF_A0H) + kind*ABUF + r*ROWP + p*16;
            CP_ASYNC16(dst, src);
        }
        CP_COMMIT();
    }

    if (tid < 128) { bS[tid] = bias[tid]; sSum[tid] = 0.f; sSq[tid] = 0.f; }
    {
        float av = g_att[attSlot*256 + tid];
        int i = tid >> 4, j = tid & 15;
        att2[tid] = (i == j) ? 0.f : av;
        if (i == j) dS[i] = av;
    }

    // ldmatrix lane addressing
    int sub = lane >> 3, lr = lane & 7;
    uint32_t aOffRow = ((sub & 1)*8 + lr)*ROWP + (sub >> 1)*16;   // within a 16-row mt block
    int brow = wn*64 + ((lane >> 4) & 1)*8 + lr;
    int bkh  = (lane >> 3) & 1;
    uint32_t bAddrH = sbase + OFF_WH + brow*ROWP + bkh*16;
    uint32_t bAddrL = sbase + OFF_WL + brow*ROWP + bkh*16;
    int g = lane >> 2, tg = lane & 3;

    uint32_t aH = sbase + (wm ? OFF_A1H : OFF_A0H) + aOffRow;
    uint32_t aL = aH + ABUF;

    for (int pp = 0; pp < npairs; pp++) {
        long pairRow = (long)(chunk0 + pp*2) * 64;

        CP_WAIT0();
        __syncthreads();

        // ---- mainloop: 64x64 warp tile, B shared across 4 mt blocks (ratio 6) ----
        float acc[4][8][4];
        #pragma unroll
        for (int mt = 0; mt < 4; mt++)
            #pragma unroll
            for (int nt = 0; nt < 8; nt++)
                #pragma unroll
                for (int q = 0; q < 4; q++) acc[mt][nt][q] = 0.f;

        #pragma unroll
        for (int ks = 0; ks < 8; ks++) {
            uint32_t ah[4][4], al[4][4];
            #pragma unroll
            for (int mt = 0; mt < 4; mt++) {
                ldsm4(ah[mt], aH + ks*32 + mt*16*ROWP);
                ldsm4(al[mt], aL + ks*32 + mt*16*ROWP);
            }
            #pragma unroll
            for (int pr = 0; pr < 4; pr++) {
                uint32_t bh[4], bl[4];
                ldsm4(bh, bAddrH + ks*32 + pr*16*ROWP);
                ldsm4(bl, bAddrL + ks*32 + pr*16*ROWP);
                #pragma unroll
                for (int hf = 0; hf < 2; hf++) {
                    int nt = pr*2 + hf;
                    #pragma unroll
                    for (int mt = 0; mt < 4; mt++) {
                        mma16816(acc[mt][nt], ah[mt], bh + hf*2);
                        mma16816(acc[mt][nt], al[mt], bh + hf*2);
                        mma16816(acc[mt][nt], ah[mt], bl + hf*2);
                    }
                }
            }
        }
        __syncthreads();   // A pair consumed -> regions reused as C buffers

        // ---- chunk-major epilogue ----
        // chunk c2 uses its own A region: Cb0[64][66] then Cb1[64][66].
        // Pass ii: warps (wm==c2, wn==ii) store C0 block ii; (wm==c2, wn==ii+2)
        // store C1 block ii; all 256 threads mix channels ii*64..+63 for chunk c2.
        #pragma unroll
        for (int c2 = 0; c2 < 2; c2++) {
            const float* Cb0r = (const float*)(dsm + c2*(2*ABUF));
            const float* Cb1r = Cb0r + 64*66;
            #pragma unroll
            for (int ii = 0; ii < 2; ii++) {
                if (wm == c2 && (wn == ii || wn == ii + 2)) {
                    float* Cb = (float*)(dsm + c2*(2*ABUF)) + ((wn >= 2) ? 64*66 : 0);
                    #pragma unroll
                    for (int mt = 0; mt < 4; mt++) {
                        int rb = mt*16 + g;
                        #pragma unroll
                        for (int nt = 0; nt < 8; nt++) {
                            int lc = nt*8 + tg*2;
                            float2 v0; v0.x = acc[mt][nt][0]; v0.y = acc[mt][nt][1];
                            float2 v1; v1.x = acc[mt][nt][2]; v1.y = acc[mt][nt][3];
                            *(float2*)(Cb + rb*66 + lc)     = v0;
                            *(float2*)(Cb + (rb+8)*66 + lc) = v1;
                        }
                    }
                }
                __syncthreads();
                {
                    int si = tid >> 6;             // sample 0..3
                    int c  = tid & 63;             // local column
                    int ch = ii*64 + c;            // output channel
                    float a[16];
                    float bb = bS[ch];
                    #pragma unroll
                    for (int i = 0; i < 16; i++)
                        a[i] = fmaf(dS[i], Cb0r[(si*16+i)*66 + c], bb);
                    #pragma unroll
                    for (int j = 0; j < 16; j++) {
                        float v = Cb1r[(si*16+j)*66 + c];
                        #pragma unroll
                        for (int i = 0; i < 16; i++)
                            a[i] = fmaf(att2[i*16+j], v, a[i]);
                    }
                    float cs = 0.f, cq = 0.f;
                    long rbase = pairRow + c2*64 + si*16;
                    #pragma unroll
                    for (int i = 0; i < 16; i++) {
                        Hout[(rbase + i)*128 + ch] = a[i];
                        cs += a[i]; cq += a[i]*a[i];
                    }
                    atomicAdd(&sSum[ch], cs);
                    atomicAdd(&sSq[ch],  cq);
                }
                __syncthreads();
            }
            // ---- chunk c2's region is free: prefetch its next-pair data now ----
            if (pp + 1 < npairs) {
                long rowC = (long)(chunk0 + (pp+1)*2 + c2) * 64;
                #pragma unroll
                for (int j = 0; j < 8; j++) {
                    int idx = tid + j*256;         // 2048 pieces (64 rows x hi/lo)
                    int kind = idx >> 10;
                    int rem  = idx & 1023;
                    int r = rem >> 4, p = rem & 15;
                    const char* src = (const char*)(kind ? Xl : Xh) + (rowC + r)*256 + p*16;
                    uint32_t dst = sbase + (c2 ? OFF_A1H : OFF_A0H) + kind*ABUF + r*ROWP + p*16;
                    CP_ASYNC16(dst, src);
                }
                CP_COMMIT();
            }
        }
    }
    __syncthreads();
    if (tid < 128) {
        atomicAdd(&g_sum  [slotOut*512 + set*128 + tid], (double)sSum[tid]);
        atomicAdd(&g_sumsq[slotOut*512 + set*128 + tid], (double)sSq[tid]);
    }
}

// ---------------- output semgconv (128 -> 3), hi/lo input ----------------
__global__ void sg_gconv_out(const __nv_bfloat16* __restrict__ Xh, const __nv_bfloat16* __restrict__ Xl,
                             const float* __restrict__ Wout, const float* __restrict__ bout,
                             int finalMode, float* __restrict__ outp, float* __restrict__ merged)
{
    __shared__ float xs[4*16*129];
    __shared__ float Wl[768];
    __shared__ float attL[256];
    __shared__ float h1s[4][16][3];
    __shared__ float bL[3];
    int t  = threadIdx.x;              // 128
    int s0 = blockIdx.x * 4;
    int branch = finalMode ? 4 : (s0 >> 13);

    for (int i = t; i < 768; i += 128) Wl[i] = Wout[branch*768 + i];
    for (int i = t; i < 256; i += 128) attL[i] = g_att[(10+branch)*256 + i];
    if (t < 3) bL[t] = bout[branch*3 + t];
    for (int i = t; i < 4*16*128; i += 128) {
        int s = i >> 11, rem = i & 2047, j = rem >> 7, k = rem & 127;
        long gi = ((long)(s0+s)*16 + j)*128 + k;
        xs[(s*16+j)*129 + k] = __bfloat162float(Xh[gi]) + __bfloat162float(Xl[gi]);
    }
    __syncthreads();

    int si = t >> 4, ji = t & 15;
    float h0[3] = {0.f,0.f,0.f};
    if (t < 64) {
        float h1[3] = {0.f,0.f,0.f};
        const float* xr = xs + (si*16 + ji)*129;
        for (int k = 0; k < 128; k++) {
            float x = xr[k];
            h0[0] += x*Wl[k*3+0]; h0[1] += x*Wl[k*3+1]; h0[2] += x*Wl[k*3+2];
            h1[0] += x*Wl[384+k*3+0]; h1[1] += x*Wl[384+k*3+1]; h1[2] += x*Wl[384+k*3+2];
        }
        h1s[si][ji][0]=h1[0]; h1s[si][ji][1]=h1[1]; h1s[si][ji][2]=h1[2];
    }
    __syncthreads();
    if (t < 64) {
        float dd = attL[ji*17];
        float o[3];
        #pragma unroll
        for (int c = 0; c < 3; c++) o[c] = dd*h0[c] + bL[c];
        #pragma unroll
        for (int j = 0; j < 16; j++) {
            if (j == ji) continue;
            float a = attL[ji*16 + j];
            o[0] += a*h1s[si][j][0]; o[1] += a*h1s[si][j][1]; o[2] += a*h1s[si][j][2];
        }
        if (finalMode) {
            long row = ((long)(s0+si)*16 + ji)*3;
            outp[row+0]=o[0]; outp[row+1]=o[1]; outp[row+2]=o[2];
        } else {
            int loc = (s0+si) & (BB-1);
            long ob = (long)(1+branch)*BB*48 + ((long)loc*16 + ji)*3;
            outp[ob+0]=o[0]; outp[ob+1]=o[1]; outp[ob+2]=o[2];
            long mb = ((long)loc*16 + ji)*12 + branch*3;
            merged[mb+0]=o[0]; merged[mb+1]=o[1]; merged[mb+2]=o[2];
        }
    }
}

// ---------------- host orchestration ----------------
extern "C" void kernel_launch(void* const* d_in, const int* in_sizes, int n_in,
                              void* d_out, int out_size)
{
    const float* x1       = (const float*)d_in[0];
    const float* x2       = (const float*)d_in[1];
    const float* x3       = (const float*)d_in[2];
    const float* x4       = (const float*)d_in[3];
    const float* W_in     = (const float*)d_in[4];
    const float* b_in     = (const float*)d_in[5];
    const float* e_in     = (const float*)d_in[6];
    const float* g_in     = (const float*)d_in[7];
    const float* beta_in  = (const float*)d_in[8];
    const float* W_cat    = (const float*)d_in[9];
    const float* b_cat    = (const float*)d_in[10];
    const float* e_cat    = (const float*)d_in[11];
    const float* g_cat    = (const float*)d_in[12];
    const float* beta_cat = (const float*)d_in[13];
    const float* W_res    = (const float*)d_in[14];
    const float* b_res    = (const float*)d_in[15];
    const float* e_res    = (const float*)d_in[16];
    const float* g_res    = (const float*)d_in[17];
    const float* beta_res = (const float*)d_in[18];
    const float* W_out    = (const float*)d_in[19];
    const float* b_out    = (const float*)d_in[20];
    const float* e_out    = (const float*)d_in[21];
    float* out = (float*)d_out;

    float *Hb, *Mb;
    __nv_bfloat16 *Xh0, *Xl0, *Xh1, *Xl1, *Wb;
    cudaGetSymbolAddress((void**)&Hb,  g_H);
    cudaGetSymbolAddress((void**)&Mb,  g_merged);
    cudaGetSymbolAddress((void**)&Xh0, g_Xh0);
    cudaGetSymbolAddress((void**)&Xl0, g_Xl0);
    cudaGetSymbolAddress((void**)&Xh1, g_Xh1);
    cudaGetSymbolAddress((void**)&Xl1, g_Xl1);
    cudaGetSymbolAddress((void**)&Wb,  g_Wbf);

    cudaFuncSetAttribute(sg_gemm_pipe, cudaFuncAttributeMaxDynamicSharedMemorySize, GEMM_SMEM);

    sg_prep<<<1,256>>>(e_in, e_cat, e_res, e_out);
    sg_wprep<<<1024,256>>>(W_res);

    for (int phase = 0; phase < 2; phase++) {
        int nS      = phase ? BB : NS4;
        int nRows   = nS*JJ;
        int nChunks = nRows/64;
        int TPC     = phase ? 4 : 8;       // even (pairs)
        int sb      = phase*9;
        if (phase == 0)
            sg_gconv_smallk<2><<<nS/8,128>>>(x1,x2,x3,x4, 1, W_in, b_in, 0, sb, Hb);
        else
            sg_gconv_smallk<12><<<nS/8,128>>>(Mb, nullptr, nullptr, nullptr, 0, W_cat, b_cat, 1, sb, Hb);

        const float* gIn0 = phase ? g_cat : g_in;
        const float* bIn0 = phase ? beta_cat : beta_in;
        sg_convert<<<nRows/64,256>>>(Hb, nullptr, nullptr, Xh0, Xl0, gIn0, bIn0, sb);

        for (int s = 0; s < 8; s++) {
            const __nv_bfloat16* Xhi = (s & 1) ? Xh1 : Xh0;
            const __nv_bfloat16* Xli = (s & 1) ? Xl1 : Xl0;
            sg_gemm_pipe<<<nChunks/TPC, 256, GEMM_SMEM>>>(
                Xhi, Xli, Wb + (long)s*65536, b_res + s*128, 2+s, sb+s+1, TPC, Hb);
            __nv_bfloat16* Xho = (s & 1) ? Xh0 : Xh1;
            __nv_bfloat16* Xlo = (s & 1) ? Xl0 : Xl1;
            const __nv_bfloat16* Rh = (s & 1) ? Xh0 : nullptr;
            const __nv_bfloat16* Rl = (s & 1) ? Xl0 : nullptr;
            sg_convert<<<nRows/64,256>>>(Hb, Rh, Rl, Xho, Xlo,
                                         g_res + s*128, beta_res + s*128, sb+s+1);
        }
        sg_gconv_out<<<nS/4,128>>>(Xh0, Xl0, W_out, b_out, phase, out, phase ? nullptr : Mb);
    }
}

// round 15
// speedup vs baseline: 1.0945x; 1.0945x over previous
#include <cuda_runtime.h>
#include <cuda_bf16.h>
#include <cstdint>

#define BB   8192
#define JJ   16
#define NHID 128
#define NS4  (4*BB)
#define NRMAX (NS4*JJ)              // 524288 rows
#define EPSB 1e-5f
#define INVN (1.0/131072.0)

// smem layout (bytes), 272B padded rows (conflict-free LDSM)
#define ROWP      272
#define ABUF      (64*ROWP)                     // 17408 per (hi or lo) 64-row buffer
#define OFF_A0H   0
#define OFF_A0L   ABUF
#define OFF_A1H   (2*ABUF)
#define OFF_A1L   (3*ABUF)
#define OFF_WH    (4*ABUF)                      // 69632
#define OFF_WL    (OFF_WH + 256*ROWP)
#define GEMM_SMEM (OFF_WL + 256*ROWP)           // 208896
#define CBS       68                            // C chunk-buffer stride (floats), 272B rows

// ---------------- persistent scratch ----------------
__device__ float         g_H  [NRMAX*NHID];
__device__ __nv_bfloat16 g_Xh0[NRMAX*NHID];
__device__ __nv_bfloat16 g_Xl0[NRMAX*NHID];
__device__ __nv_bfloat16 g_Xh1[NRMAX*NHID];
__device__ __nv_bfloat16 g_Xl1[NRMAX*NHID];
__device__ __nv_bfloat16 g_Wbf[8*2*256*128];   // [stage][hi/lo][n=256][k=128]
__device__ float  g_merged[BB*JJ*12];
__device__ float  g_att[15*JJ*JJ];
__device__ double g_sum  [18*4*NHID];          // [slot][set][128]
__device__ double g_sumsq[18*4*NHID];

__constant__ unsigned short c_mask[16] = {
 0x0093,0x0007,0x000E,0x000C,0x0031,0x0070,0x0060,0x0181,
 0x4B80,0x0700,0x0600,0x1900,0x3800,0x3000,0xC100,0xC000};

// ---------------- PTX helpers ----------------
__device__ __forceinline__ uint32_t smem_u32(const void* p) {
    uint32_t a;
    asm("{ .reg .u64 t; cvta.to.shared.u64 t, %1; cvt.u32.u64 %0, t; }" : "=r"(a) : "l"(p));
    return a;
}
__device__ __forceinline__ void mma16816(float* c, const uint32_t* a, const uint32_t* b) {
    asm volatile("mma.sync.aligned.m16n8k16.row.col.f32.bf16.bf16.f32 "
        "{%0,%1,%2,%3}, {%4,%5,%6,%7}, {%8,%9}, {%0,%1,%2,%3};"
        : "+f"(c[0]), "+f"(c[1]), "+f"(c[2]), "+f"(c[3])
        : "r"(a[0]), "r"(a[1]), "r"(a[2]), "r"(a[3]), "r"(b[0]), "r"(b[1]));
}
__device__ __forceinline__ void ldsm4(uint32_t* r, uint32_t addr) {
    asm volatile("ldmatrix.sync.aligned.m8n8.x4.shared.b16 {%0,%1,%2,%3}, [%4];"
        : "=r"(r[0]), "=r"(r[1]), "=r"(r[2]), "=r"(r[3]) : "r"(addr));
}
#define CP_ASYNC16(dst, src) asm volatile("cp.async.cg.shared.global [%0], [%1], 16;" :: "r"(dst), "l"(src))
#define CP_COMMIT()          asm volatile("cp.async.commit_group;")
#define CP_WAIT(n)           asm volatile("cp.async.wait_group %0;" :: "n"(n))

// ---------------- prep (merged): W bf16 split everywhere; block 0 also does softmax --
__global__ void sg_prep0(const float* __restrict__ W_res,
                         const float* __restrict__ e_in, const float* __restrict__ e_cat,
                         const float* __restrict__ e_res, const float* __restrict__ e_out)
{
    int t = threadIdx.x;
    // W split slice (all 1024 blocks)
    {
        int idx = blockIdx.x*256 + t;           // < 262144
        int s = idx >> 15;
        int part = (idx >> 14) & 1;
        int k = (idx >> 7) & 127;
        int c = idx & 127;
        float w = W_res[(((s*2 + part)*128) + k)*128 + c];
        __nv_bfloat16 hi = __float2bfloat16(w);
        __nv_bfloat16 lo = __float2bfloat16(w - __bfloat162float(hi));
        int n = part*128 + c;
        g_Wbf[((long)(s*2+0)*256 + n)*128 + k] = hi;
        g_Wbf[((long)(s*2+1)*256 + n)*128 + k] = lo;
    }
    if (blockIdx.x != 0) return;
    for (int i = t; i < 18*4*NHID; i += 256) { g_sum[i] = 0.0; g_sumsq[i] = 0.0; }
    if (t < 240) {
        int slot = t >> 4, i = t & 15;
        const float* e;
        if (slot == 0)      e = e_in;
        else if (slot == 1) e = e_cat;
        else if (slot < 10) e = e_res + (slot-2)*256;
        else                e = e_out + (slot-10)*256;
        unsigned m = c_mask[i];
        float mx = -1e30f;
        for (int j = 0; j < 16; j++) if ((m>>j)&1) mx = fmaxf(mx, e[i*16+j]);
        float v[16]; float s = 0.f;
        for (int j = 0; j < 16; j++) {
            float x = ((m>>j)&1) ? expf(e[i*16+j]-mx) : 0.f;
            v[j] = x; s += x;
        }
        float inv = 1.f/s;
        for (int j = 0; j < 16; j++) g_att[slot*256 + i*16 + j] = v[j]*inv;
    }
}

// ---------------- small-K input gconv (K=2 / K=12), input-space mixing ----------------
template<int KIN>
__global__ void sg_gconv_smallk(const float* __restrict__ x0, const float* __restrict__ x1,
                                const float* __restrict__ x2, const float* __restrict__ x3,
                                int fourway, const float* __restrict__ W,
                                const float* __restrict__ bias, int attSlot, int slot,
                                float* __restrict__ H)
{
    __shared__ float xs [8][16][KIN];
    __shared__ float y0s[8][16][KIN];
    __shared__ float y1s[8][16][KIN];
    __shared__ float Ws[2*KIN*NHID];
    __shared__ float attS[256];
    int t  = threadIdx.x;              // 128
    int s0 = blockIdx.x * 8;
    int set = blockIdx.x >> 10;

    for (int i = t; i < 2*KIN*NHID; i += 128) Ws[i] = W[i];
    for (int i = t; i < 256; i += 128) attS[i] = g_att[attSlot*256 + i];

    const int total = 8*16*KIN;
    for (int i = t; i < total; i += 128) {
        int s = i/(16*KIN); int rem = i - s*16*KIN; int j = rem/KIN; int k = rem - j*KIN;
        int gs = s0 + s;
        const float* xp; int loc;
        if (fourway) {
            int br = gs >> 13; loc = gs & (BB-1);
            xp = (br==0)?x0:(br==1)?x1:(br==2)?x2:x3;
        } else { xp = x0; loc = gs; }
        xs[s][j][k] = xp[(loc*16 + j)*KIN + k];
    }
    __syncthreads();
    for (int i = t; i < total; i += 128) {
        int s = i/(16*KIN); int rem = i - s*16*KIN; int ji = rem/KIN; int k = rem - ji*KIN;
        float a1 = 0.f;
        #pragma unroll
        for (int j = 0; j < 16; j++) a1 += attS[ji*16+j]*xs[s][j][k];
        a1 -= attS[ji*17]*xs[s][ji][k];
        y0s[s][ji][k] = attS[ji*17]*xs[s][ji][k];
        y1s[s][ji][k] = a1;
    }
    __syncthreads();
    int c = t;
    float w0[KIN], w1[KIN];
    #pragma unroll
    for (int k = 0; k < KIN; k++) { w0[k] = Ws[k*NHID+c]; w1[k] = Ws[(KIN+k)*NHID+c]; }
    float bb = bias[c];
    float bsum = 0.f, bsq = 0.f;
    for (int s = 0; s < 8; s++)
        for (int ji = 0; ji < 16; ji++) {
            float h = bb;
            #pragma unroll
            for (int k = 0; k < KIN; k++) h += y0s[s][ji][k]*w0[k] + y1s[s][ji][k]*w1[k];
            H[((long)(s0+s)*16 + ji)*NHID + c] = h;
            bsum += h; bsq += h*h;
        }
    atomicAdd(&g_sum  [slot*512 + set*128 + c], (double)bsum);
    atomicAdd(&g_sumsq[slot*512 + set*128 + c], (double)bsq);
}

// ---------------- convert: BN(affine from stats) + ReLU (+res) -> bf16 hi/lo --------
__global__ void sg_convert(const float* __restrict__ H,
                           const __nv_bfloat16* __restrict__ Rh, const __nv_bfloat16* __restrict__ Rl,
                           __nv_bfloat16* __restrict__ Xh, __nv_bfloat16* __restrict__ Xl,
                           const float* __restrict__ gma, const float* __restrict__ bta,
                           int slotIn)
{
    int t = threadIdx.x;               // 256
    long base = (long)blockIdx.x * 8192;   // 64 rows
    int set = blockIdx.x >> 11;
    int c0 = (t*4) & 127;
    float a[4], b[4];
    #pragma unroll
    for (int k = 0; k < 4; k++) {
        double s = g_sum  [slotIn*512 + set*128 + c0 + k];
        double q = g_sumsq[slotIn*512 + set*128 + c0 + k];
        float mu  = (float)(s*INVN);
        float var = (float)(q*INVN) - mu*mu;
        float istd = rsqrtf(var + EPSB);
        float gg = gma[c0+k];
        a[k] = istd*gg; b[k] = bta[c0+k] - mu*istd*gg;
    }
    for (int i = t*4; i < 8192; i += 1024) {
        float4 h = *(const float4*)(H + base + i);
        float v[4];
        v[0] = fmaxf(fmaf(h.x, a[0], b[0]), 0.f);
        v[1] = fmaxf(fmaf(h.y, a[1], b[1]), 0.f);
        v[2] = fmaxf(fmaf(h.z, a[2], b[2]), 0.f);
        v[3] = fmaxf(fmaf(h.w, a[3], b[3]), 0.f);
        if (Rh) {
            __nv_bfloat162 rh0 = *(const __nv_bfloat162*)(Rh + base + i);
            __nv_bfloat162 rh1 = *(const __nv_bfloat162*)(Rh + base + i + 2);
            __nv_bfloat162 rl0 = *(const __nv_bfloat162*)(Rl + base + i);
            __nv_bfloat162 rl1 = *(const __nv_bfloat162*)(Rl + base + i + 2);
            v[0] += __bfloat162float(rh0.x) + __bfloat162float(rl0.x);
            v[1] += __bfloat162float(rh0.y) + __bfloat162float(rl0.y);
            v[2] += __bfloat162float(rh1.x) + __bfloat162float(rl1.x);
            v[3] += __bfloat162float(rh1.y) + __bfloat162float(rl1.y);
        }
        __nv_bfloat16 hh[4], ll[4];
        #pragma unroll
        for (int k = 0; k < 4; k++) {
            hh[k] = __float2bfloat16(v[k]);
            ll[k] = __float2bfloat16(v[k] - __bfloat162float(hh[k]));
        }
        __nv_bfloat162 p0, p1, q0, q1;
        p0.x = hh[0]; p0.y = hh[1]; p1.x = hh[2]; p1.y = hh[3];
        q0.x = ll[0]; q0.y = ll[1]; q1.x = ll[2]; q1.y = ll[3];
        *(__nv_bfloat162*)(Xh + base + i)     = p0;
        *(__nv_bfloat162*)(Xh + base + i + 2) = p1;
        *(__nv_bfloat162*)(Xl + base + i)     = q0;
        *(__nv_bfloat162*)(Xl + base + i + 2) = q1;
    }
}

// ---------------- pipelined gemm (R9): W resident, cp.async double-buffered A -------
// 256 threads, 8 warps (2x4), warp tile 32x64 (ratio 4 mma/ldsm4).
// 64-row chunks; C = X @ [W0|W1]^T (bf16x3, fp32 acc); epilogue joint-mix + stats.
__global__ __launch_bounds__(256) void sg_gemm_pipe(
    const __nv_bfloat16* __restrict__ Xh, const __nv_bfloat16* __restrict__ Xl,
    const __nv_bfloat16* __restrict__ Wbf, const float* __restrict__ bias,
    int attSlot, int slotOut, int tpc, float* __restrict__ Hout)
{
    extern __shared__ char dsm[];
    __shared__ float att2[256];
    __shared__ float dS[16];
    __shared__ float bS[128];
    __shared__ float sSum[128], sSq[128];

    int tid = threadIdx.x, wid = tid >> 5, lane = tid & 31;
    int wm = wid >> 2, wn = wid & 3;   // 2x4 warp grid, warp tile 32(M) x 64(N)
    int chunk0 = blockIdx.x * tpc;
    int set = chunk0 >> 11;            // 2048 chunks per BN set
    uint32_t sbase = smem_u32(dsm);

    // ---- G0: W (hi+lo) + A chunk0 ----
    {
        const char* wsrc = (const char*)Wbf;
        #pragma unroll
        for (int j = 0; j < 32; j++) {
            int idx = tid + j*256;             // 8192 W pieces
            int kind = idx >> 12, rem = idx & 4095;
            int r = rem >> 4, p = rem & 15;
            uint32_t dst = sbase + (kind ? OFF_WL : OFF_WH) + r*ROWP + p*16;
            CP_ASYNC16(dst, wsrc + kind*65536 + r*256 + p*16);
        }
        long row0 = (long)chunk0 * 64;
        #pragma unroll
        for (int j = 0; j < 8; j++) {
            int idx = tid + j*256;             // 2048 A pieces
            int kind = idx >> 10, rem = idx & 1023;
            int r = rem >> 4, p = rem & 15;
            const char* src = (const char*)(kind ? Xl : Xh) + (row0 + r)*256 + p*16;
            uint32_t dst = sbase + OFF_A0H + kind*ABUF + r*ROWP + p*16;
            CP_ASYNC16(dst, src);
        }
        CP_COMMIT();
    }
    // ---- G1: A chunk1 ----
    if (tpc > 1) {
        long row0 = (long)(chunk0 + 1) * 64;
        #pragma unroll
        for (int j = 0; j < 8; j++) {
            int idx = tid + j*256;
            int kind = idx >> 10, rem = idx & 1023;
            int r = rem >> 4, p = rem & 15;
            const char* src = (const char*)(kind ? Xl : Xh) + (row0 + r)*256 + p*16;
            uint32_t dst = sbase + OFF_A1H + kind*ABUF + r*ROWP + p*16;
            CP_ASYNC16(dst, src);
        }
        CP_COMMIT();
    }

    if (tid < 128) { bS[tid] = bias[tid]; sSum[tid] = 0.f; sSq[tid] = 0.f; }
    {
        float av = g_att[attSlot*256 + tid];
        int i = tid >> 4, j = tid & 15;
        att2[tid] = (i == j) ? 0.f : av;
        if (i == j) dS[i] = av;
    }

    // ldmatrix lane addressing
    int sub = lane >> 3, lr = lane & 7;
    int arow = wm*32 + (sub & 1)*8 + lr;
    uint32_t aOffRow = arow*ROWP + (sub >> 1)*16;          // add buffer base
    int brow = wn*64 + ((lane >> 4) & 1)*8 + lr;
    int bkh  = (lane >> 3) & 1;
    uint32_t bAddrH = sbase + OFF_WH + brow*ROWP + bkh*16;
    uint32_t bAddrL = sbase + OFF_WL + brow*ROWP + bkh*16;
    int g = lane >> 2, tg = lane & 3;

    for (int tt = 0; tt < tpc; tt++) {
        long row0 = (long)(chunk0 + tt) * 64;
        uint32_t aH = sbase + ((tt & 1) ? OFF_A1H : OFF_A0H) + aOffRow;
        uint32_t aL = aH + ABUF;

        if (tt + 1 < tpc) CP_WAIT(1); else CP_WAIT(0);
        __syncthreads();

        // ---- mainloop ----
        float acc[2][8][4];
        #pragma unroll
        for (int mt = 0; mt < 2; mt++)
            #pragma unroll
            for (int nt = 0; nt < 8; nt++)
                #pragma unroll
                for (int q = 0; q < 4; q++) acc[mt][nt][q] = 0.f;

        #pragma unroll
        for (int ks = 0; ks < 8; ks++) {
            uint32_t ah[2][4], al[2][4];
            ldsm4(ah[0], aH + ks*32);
            ldsm4(ah[1], aH + ks*32 + 16*ROWP);
            ldsm4(al[0], aL + ks*32);
            ldsm4(al[1], aL + ks*32 + 16*ROWP);
            #pragma unroll
            for (int pr = 0; pr < 4; pr++) {
                uint32_t bh[4], bl[4];
                ldsm4(bh, bAddrH + ks*32 + pr*16*ROWP);
                ldsm4(bl, bAddrL + ks*32 + pr*16*ROWP);
                #pragma unroll
                for (int hf = 0; hf < 2; hf++) {
                    int nt = pr*2 + hf;
                    #pragma unroll
                    for (int mt = 0; mt < 2; mt++) {
                        mma16816(acc[mt][nt], ah[mt], bh + hf*2);
                        mma16816(acc[mt][nt], al[mt], bh + hf*2);
                        mma16816(acc[mt][nt], ah[mt], bl + hf*2);
                    }
                }
            }
        }
        __syncthreads();   // A buffer consumed -> reuse as C chunk buffers

        float* Cb0 = (float*)(dsm + ((tt & 1) ? OFF_A1H : OFF_A0H));
        float* Cb1 = Cb0 + 64*CBS;

        // ---- epilogue: two 64-col passes of output-space joint mix ----
        // pass ii: wn==ii stores C0 cols ii*64.., wn==ii+2 stores C1 cols 128+ii*64..
        #pragma unroll
        for (int ii = 0; ii < 2; ii++) {
            if ((wn & 1) == ii) {
                float* Cb = (wn < 2) ? Cb0 : Cb1;
                #pragma unroll
                for (int mt = 0; mt < 2; mt++) {
                    int rb = wm*32 + mt*16 + g;
                    #pragma unroll
                    for (int nt = 0; nt < 8; nt++) {
                        int lc = nt*8 + tg*2;
                        float2 v0; v0.x = acc[mt][nt][0]; v0.y = acc[mt][nt][1];
                        float2 v1; v1.x = acc[mt][nt][2]; v1.y = acc[mt][nt][3];
                        *(float2*)(Cb + rb*CBS + lc)     = v0;
                        *(float2*)(Cb + (rb+8)*CBS + lc) = v1;
                    }
                }
            }
            __syncthreads();
            {
                int si = tid >> 6;             // sample 0..3
                int c  = tid & 63;             // local column
                int ch = ii*64 + c;            // output channel
                float a[16];
                float bb = bS[ch];
                #pragma unroll
                for (int i = 0; i < 16; i++)
                    a[i] = fmaf(dS[i], Cb0[(si*16+i)*CBS + c], bb);
                #pragma unroll
                for (int j = 0; j < 16; j++) {
                    float v = Cb1[(si*16+j)*CBS + c];
                    #pragma unroll
                    for (int i = 0; i < 16; i++)
                        a[i] = fmaf(att2[i*16+j], v, a[i]);
                }
                float cs = 0.f, cq = 0.f;
                #pragma unroll
                for (int i = 0; i < 16; i++) {
                    Hout[(row0 + si*16 + i)*128 + ch] = a[i];
                    cs += a[i]; cq += a[i]*a[i];
                }
                atomicAdd(&sSum[ch], cs);
                atomicAdd(&sSq[ch],  cq);
            }
            __syncthreads();
        }

        // ---- prefetch chunk tt+2 into the buffer just freed ----
        if (tt + 2 < tpc) {
            long rowN = (long)(chunk0 + tt + 2) * 64;
            #pragma unroll
            for (int j = 0; j < 8; j++) {
                int idx = tid + j*256;
                int kind = idx >> 10, rem = idx & 1023;
                int r = rem >> 4, p = rem & 15;
                const char* src = (const char*)(kind ? Xl : Xh) + (rowN + r)*256 + p*16;
                uint32_t dst = sbase + ((tt & 1) ? OFF_A1H : OFF_A0H) + kind*ABUF + r*ROWP + p*16;
                CP_ASYNC16(dst, src);
            }
        }
        CP_COMMIT();   // uniform group counting (empty group ok)
    }
    __syncthreads();
    if (tid < 128) {
        atomicAdd(&g_sum  [slotOut*512 + set*128 + tid], (double)sSum[tid]);
        atomicAdd(&g_sumsq[slotOut*512 + set*128 + tid], (double)sSq[tid]);
    }
}

// ---------------- output semgconv (128 -> 3), hi/lo input ----------------
__global__ void sg_gconv_out(const __nv_bfloat16* __restrict__ Xh, const __nv_bfloat16* __restrict__ Xl,
                             const float* __restrict__ Wout, const float* __restrict__ bout,
                             int finalMode, float* __restrict__ outp, float* __restrict__ merged)
{
    __shared__ float xs[4*16*129];
    __shared__ float Wl[768];
    __shared__ float attL[256];
    __shared__ float h1s[4][16][3];
    __shared__ float bL[3];
    int t  = threadIdx.x;              // 128
    int s0 = blockIdx.x * 4;
    int branch = finalMode ? 4 : (s0 >> 13);

    for (int i = t; i < 768; i += 128) Wl[i] = Wout[branch*768 + i];
    for (int i = t; i < 256; i += 128) attL[i] = g_att[(10+branch)*256 + i];
    if (t < 3) bL[t] = bout[branch*3 + t];
    for (int i = t; i < 4*16*128; i += 128) {
        int s = i >> 11, rem = i & 2047, j = rem >> 7, k = rem & 127;
        long gi = ((long)(s0+s)*16 + j)*128 + k;
        xs[(s*16+j)*129 + k] = __bfloat162float(Xh[gi]) + __bfloat162float(Xl[gi]);
    }
    __syncthreads();

    int si = t >> 4, ji = t & 15;
    float h0[3] = {0.f,0.f,0.f};
    if (t < 64) {
        float h1[3] = {0.f,0.f,0.f};
        const float* xr = xs + (si*16 + ji)*129;
        for (int k = 0; k < 128; k++) {
            float x = xr[k];
            h0[0] += x*Wl[k*3+0]; h0[1] += x*Wl[k*3+1]; h0[2] += x*Wl[k*3+2];
            h1[0] += x*Wl[384+k*3+0]; h1[1] += x*Wl[384+k*3+1]; h1[2] += x*Wl[384+k*3+2];
        }
        h1s[si][ji][0]=h1[0]; h1s[si][ji][1]=h1[1]; h1s[si][ji][2]=h1[2];
    }
    __syncthreads();
    if (t < 64) {
        float dd = attL[ji*17];
        float o[3];
        #pragma unroll
        for (int c = 0; c < 3; c++) o[c] = dd*h0[c] + bL[c];
        #pragma unroll
        for (int j = 0; j < 16; j++) {
            if (j == ji) continue;
            float a = attL[ji*16 + j];
            o[0] += a*h1s[si][j][0]; o[1] += a*h1s[si][j][1]; o[2] += a*h1s[si][j][2];
        }
        if (finalMode) {
            long row = ((long)(s0+si)*16 + ji)*3;
            outp[row+0]=o[0]; outp[row+1]=o[1]; outp[row+2]=o[2];
        } else {
            int loc = (s0+si) & (BB-1);
            long ob = (long)(1+branch)*BB*48 + ((long)loc*16 + ji)*3;
            outp[ob+0]=o[0]; outp[ob+1]=o[1]; outp[ob+2]=o[2];
            long mb = ((long)loc*16 + ji)*12 + branch*3;
            merged[mb+0]=o[0]; merged[mb+1]=o[1]; merged[mb+2]=o[2];
        }
    }
}

// ---------------- host orchestration ----------------
extern "C" void kernel_launch(void* const* d_in, const int* in_sizes, int n_in,
                              void* d_out, int out_size)
{
    const float* x1       = (const float*)d_in[0];
    const float* x2       = (const float*)d_in[1];
    const float* x3       = (const float*)d_in[2];
    const float* x4       = (const float*)d_in[3];
    const float* W_in     = (const float*)d_in[4];
    const float* b_in     = (const float*)d_in[5];
    const float* e_in     = (const float*)d_in[6];
    const float* g_in     = (const float*)d_in[7];
    const float* beta_in  = (const float*)d_in[8];
    const float* W_cat    = (const float*)d_in[9];
    const float* b_cat    = (const float*)d_in[10];
    const float* e_cat    = (const float*)d_in[11];
    const float* g_cat    = (const float*)d_in[12];
    const float* beta_cat = (const float*)d_in[13];
    const float* W_res    = (const float*)d_in[14];
    const float* b_res    = (const float*)d_in[15];
    const float* e_res    = (const float*)d_in[16];
    const float* g_res    = (const float*)d_in[17];
    const float* beta_res = (const float*)d_in[18];
    const float* W_out    = (const float*)d_in[19];
    const float* b_out    = (const float*)d_in[20];
    const float* e_out    = (const float*)d_in[21];
    float* out = (float*)d_out;

    float *Hb, *Mb;
    __nv_bfloat16 *Xh0, *Xl0, *Xh1, *Xl1, *Wb;
    cudaGetSymbolAddress((void**)&Hb,  g_H);
    cudaGetSymbolAddress((void**)&Mb,  g_merged);
    cudaGetSymbolAddress((void**)&Xh0, g_Xh0);
    cudaGetSymbolAddress((void**)&Xl0, g_Xl0);
    cudaGetSymbolAddress((void**)&Xh1, g_Xh1);
    cudaGetSymbolAddress((void**)&Xl1, g_Xl1);
    cudaGetSymbolAddress((void**)&Wb,  g_Wbf);

    cudaFuncSetAttribute(sg_gemm_pipe, cudaFuncAttributeMaxDynamicSharedMemorySize, GEMM_SMEM);

    sg_prep0<<<1024,256>>>(W_res, e_in, e_cat, e_res, e_out);

    for (int phase = 0; phase < 2; phase++) {
        int nS      = phase ? BB : NS4;
        int nRows   = nS*JJ;
        int nChunks = nRows/64;
        int TPC     = phase ? 2 : 8;
        int sb      = phase*9;
        if (phase == 0)
            sg_gconv_smallk<2><<<nS/8,128>>>(x1,x2,x3,x4, 1, W_in, b_in, 0, sb, Hb);
        else
            sg_gconv_smallk<12><<<nS/8,128>>>(Mb, nullptr, nullptr, nullptr, 0, W_cat, b_cat, 1, sb, Hb);

        const float* gIn0 = phase ? g_cat : g_in;
        const float* bIn0 = phase ? beta_cat : beta_in;
        sg_convert<<<nRows/64,256>>>(Hb, nullptr, nullptr, Xh0, Xl0, gIn0, bIn0, sb);

        for (int s = 0; s < 8; s++) {
            const __nv_bfloat16* Xhi = (s & 1) ? Xh1 : Xh0;
            const __nv_bfloat16* Xli = (s & 1) ? Xl1 : Xl0;
            sg_gemm_pipe<<<nChunks/TPC, 256, GEMM_SMEM>>>(
                Xhi, Xli, Wb + (long)s*65536, b_res + s*128, 2+s, sb+s+1, TPC, Hb);
            __nv_bfloat16* Xho = (s & 1) ? Xh0 : Xh1;
            __nv_bfloat16* Xlo = (s & 1) ? Xl0 : Xl1;
            const __nv_bfloat16* Rh = (s & 1) ? Xh0 : nullptr;
            const __nv_bfloat16* Rl = (s & 1) ? Xl0 : nullptr;
            sg_convert<<<nRows/64,256>>>(Hb, Rh, Rl, Xho, Xlo,
                                         g_res + s*128, beta_res + s*128, sb+s+1);
        }
        sg_gconv_out<<<nS/4,128>>>(Xh0, Xl0, W_out, b_out, phase, out, phase ? nullptr : Mb);
    }
}

// round 16
// speedup vs baseline: 1.1713x; 1.0701x over previous
#include <cuda_runtime.h>
#include <cuda_bf16.h>
#include <cstdint>

#define BB   8192
#define JJ   16
#define NHID 128
#define NS4  (4*BB)
#define NRMAX (NS4*JJ)              // 524288 rows
#define EPSB 1e-5f
#define INVN (1.0/131072.0)

// smem layout (bytes), 272B padded rows (conflict-free LDSM)
#define ROWP      272
#define ABUF      (64*ROWP)                     // 17408 per (hi or lo) 64-row buffer
#define WBUF      (128*ROWP)                    // 34816 per (hi or lo) 128-row W half
#define OFF_AH    0
#define OFF_AL    ABUF
#define OFF_WH    (2*ABUF)                      // 34816
#define OFF_WL    (OFF_WH + WBUF)               // 69632
#define GEMM_SMEM (OFF_WL + WBUF)               // 104448  -> 2 CTAs/SM
#define CBS       136                           // C buffer stride (floats), 544B rows

// ---------------- persistent scratch ----------------
__device__ float         g_H  [NRMAX*NHID];
__device__ __nv_bfloat16 g_Xh0[NRMAX*NHID];
__device__ __nv_bfloat16 g_Xl0[NRMAX*NHID];
__device__ __nv_bfloat16 g_Xh1[NRMAX*NHID];
__device__ __nv_bfloat16 g_Xl1[NRMAX*NHID];
__device__ __nv_bfloat16 g_Wbf[8*2*256*128];   // [stage][hi/lo][n=256][k=128]
__device__ float  g_merged[BB*JJ*12];
__device__ float  g_att[15*JJ*JJ];
__device__ double g_sum  [18*4*NHID];          // [slot][set][128]
__device__ double g_sumsq[18*4*NHID];

__constant__ unsigned short c_mask[16] = {
 0x0093,0x0007,0x000E,0x000C,0x0031,0x0070,0x0060,0x0181,
 0x4B80,0x0700,0x0600,0x1900,0x3800,0x3000,0xC100,0xC000};

// ---------------- PTX helpers ----------------
__device__ __forceinline__ uint32_t smem_u32(const void* p) {
    uint32_t a;
    asm("{ .reg .u64 t; cvta.to.shared.u64 t, %1; cvt.u32.u64 %0, t; }" : "=r"(a) : "l"(p));
    return a;
}
__device__ __forceinline__ void mma16816(float* c, const uint32_t* a, const uint32_t* b) {
    asm volatile("mma.sync.aligned.m16n8k16.row.col.f32.bf16.bf16.f32 "
        "{%0,%1,%2,%3}, {%4,%5,%6,%7}, {%8,%9}, {%0,%1,%2,%3};"
        : "+f"(c[0]), "+f"(c[1]), "+f"(c[2]), "+f"(c[3])
        : "r"(a[0]), "r"(a[1]), "r"(a[2]), "r"(a[3]), "r"(b[0]), "r"(b[1]));
}
__device__ __forceinline__ void ldsm4(uint32_t* r, uint32_t addr) {
    asm volatile("ldmatrix.sync.aligned.m8n8.x4.shared.b16 {%0,%1,%2,%3}, [%4];"
        : "=r"(r[0]), "=r"(r[1]), "=r"(r[2]), "=r"(r[3]) : "r"(addr));
}
#define CP_ASYNC16(dst, src) asm volatile("cp.async.cg.shared.global [%0], [%1], 16;" :: "r"(dst), "l"(src))
#define CP_COMMIT()          asm volatile("cp.async.commit_group;")
#define CP_WAIT0()           asm volatile("cp.async.wait_group 0;")

// ---------------- prep (merged): W bf16 split everywhere; block 0 also does softmax --
__global__ void sg_prep0(const float* __restrict__ W_res,
                         const float* __restrict__ e_in, const float* __restrict__ e_cat,
                         const float* __restrict__ e_res, const float* __restrict__ e_out)
{
    int t = threadIdx.x;
    {
        int idx = blockIdx.x*256 + t;           // < 262144
        int s = idx >> 15;
        int part = (idx >> 14) & 1;
        int k = (idx >> 7) & 127;
        int c = idx & 127;
        float w = W_res[(((s*2 + part)*128) + k)*128 + c];
        __nv_bfloat16 hi = __float2bfloat16(w);
        __nv_bfloat16 lo = __float2bfloat16(w - __bfloat162float(hi));
        int n = part*128 + c;
        g_Wbf[((long)(s*2+0)*256 + n)*128 + k] = hi;
        g_Wbf[((long)(s*2+1)*256 + n)*128 + k] = lo;
    }
    if (blockIdx.x != 0) return;
    for (int i = t; i < 18*4*NHID; i += 256) { g_sum[i] = 0.0; g_sumsq[i] = 0.0; }
    if (t < 240) {
        int slot = t >> 4, i = t & 15;
        const float* e;
        if (slot == 0)      e = e_in;
        else if (slot == 1) e = e_cat;
        else if (slot < 10) e = e_res + (slot-2)*256;
        else                e = e_out + (slot-10)*256;
        unsigned m = c_mask[i];
        float mx = -1e30f;
        for (int j = 0; j < 16; j++) if ((m>>j)&1) mx = fmaxf(mx, e[i*16+j]);
        float v[16]; float s = 0.f;
        for (int j = 0; j < 16; j++) {
            float x = ((m>>j)&1) ? expf(e[i*16+j]-mx) : 0.f;
            v[j] = x; s += x;
        }
        float inv = 1.f/s;
        for (int j = 0; j < 16; j++) g_att[slot*256 + i*16 + j] = v[j]*inv;
    }
}

// ---------------- small-K input gconv (K=2 / K=12), input-space mixing ----------------
template<int KIN>
__global__ void sg_gconv_smallk(const float* __restrict__ x0, const float* __restrict__ x1,
                                const float* __restrict__ x2, const float* __restrict__ x3,
                                int fourway, const float* __restrict__ W,
                                const float* __restrict__ bias, int attSlot, int slot,
                                float* __restrict__ H)
{
    __shared__ float xs [8][16][KIN];
    __shared__ float y0s[8][16][KIN];
    __shared__ float y1s[8][16][KIN];
    __shared__ float Ws[2*KIN*NHID];
    __shared__ float attS[256];
    int t  = threadIdx.x;              // 128
    int s0 = blockIdx.x * 8;
    int set = blockIdx.x >> 10;

    for (int i = t; i < 2*KIN*NHID; i += 128) Ws[i] = W[i];
    for (int i = t; i < 256; i += 128) attS[i] = g_att[attSlot*256 + i];

    const int total = 8*16*KIN;
    for (int i = t; i < total; i += 128) {
        int s = i/(16*KIN); int rem = i - s*16*KIN; int j = rem/KIN; int k = rem - j*KIN;
        int gs = s0 + s;
        const float* xp; int loc;
        if (fourway) {
            int br = gs >> 13; loc = gs & (BB-1);
            xp = (br==0)?x0:(br==1)?x1:(br==2)?x2:x3;
        } else { xp = x0; loc = gs; }
        xs[s][j][k] = xp[(loc*16 + j)*KIN + k];
    }
    __syncthreads();
    for (int i = t; i < total; i += 128) {
        int s = i/(16*KIN); int rem = i - s*16*KIN; int ji = rem/KIN; int k = rem - ji*KIN;
        float a1 = 0.f;
        #pragma unroll
        for (int j = 0; j < 16; j++) a1 += attS[ji*16+j]*xs[s][j][k];
        a1 -= attS[ji*17]*xs[s][ji][k];
        y0s[s][ji][k] = attS[ji*17]*xs[s][ji][k];
        y1s[s][ji][k] = a1;
    }
    __syncthreads();
    int c = t;
    float w0[KIN], w1[KIN];
    #pragma unroll
    for (int k = 0; k < KIN; k++) { w0[k] = Ws[k*NHID+c]; w1[k] = Ws[(KIN+k)*NHID+c]; }
    float bb = bias[c];
    float bsum = 0.f, bsq = 0.f;
    for (int s = 0; s < 8; s++)
        for (int ji = 0; ji < 16; ji++) {
            float h = bb;
            #pragma unroll
            for (int k = 0; k < KIN; k++) h += y0s[s][ji][k]*w0[k] + y1s[s][ji][k]*w1[k];
            H[((long)(s0+s)*16 + ji)*NHID + c] = h;
            bsum += h; bsq += h*h;
        }
    atomicAdd(&g_sum  [slot*512 + set*128 + c], (double)bsum);
    atomicAdd(&g_sumsq[slot*512 + set*128 + c], (double)bsq);
}

// ---------------- convert: BN(affine from stats) + ReLU (+res) -> bf16 hi/lo --------
__global__ void sg_convert(const float* __restrict__ H,
                           const __nv_bfloat16* __restrict__ Rh, const __nv_bfloat16* __restrict__ Rl,
                           __nv_bfloat16* __restrict__ Xh, __nv_bfloat16* __restrict__ Xl,
                           const float* __restrict__ gma, const float* __restrict__ bta,
                           int slotIn)
{
    int t = threadIdx.x;               // 256
    long base = (long)blockIdx.x * 8192;   // 64 rows
    int set = blockIdx.x >> 11;
    int c0 = (t*4) & 127;
    float a[4], b[4];
    #pragma unroll
    for (int k = 0; k < 4; k++) {
        double s = g_sum  [slotIn*512 + set*128 + c0 + k];
        double q = g_sumsq[slotIn*512 + set*128 + c0 + k];
        float mu  = (float)(s*INVN);
        float var = (float)(q*INVN) - mu*mu;
        float istd = rsqrtf(var + EPSB);
        float gg = gma[c0+k];
        a[k] = istd*gg; b[k] = bta[c0+k] - mu*istd*gg;
    }
    for (int i = t*4; i < 8192; i += 1024) {
        float4 h = *(const float4*)(H + base + i);
        float v[4];
        v[0] = fmaxf(fmaf(h.x, a[0], b[0]), 0.f);
        v[1] = fmaxf(fmaf(h.y, a[1], b[1]), 0.f);
        v[2] = fmaxf(fmaf(h.z, a[2], b[2]), 0.f);
        v[3] = fmaxf(fmaf(h.w, a[3], b[3]), 0.f);
        if (Rh) {
            __nv_bfloat162 rh0 = *(const __nv_bfloat162*)(Rh + base + i);
            __nv_bfloat162 rh1 = *(const __nv_bfloat162*)(Rh + base + i + 2);
            __nv_bfloat162 rl0 = *(const __nv_bfloat162*)(Rl + base + i);
            __nv_bfloat162 rl1 = *(const __nv_bfloat162*)(Rl + base + i + 2);
            v[0] += __bfloat162float(rh0.x) + __bfloat162float(rl0.x);
            v[1] += __bfloat162float(rh0.y) + __bfloat162float(rl0.y);
            v[2] += __bfloat162float(rh1.x) + __bfloat162float(rl1.x);
            v[3] += __bfloat162float(rh1.y) + __bfloat162float(rl1.y);
        }
        __nv_bfloat16 hh[4], ll[4];
        #pragma unroll
        for (int k = 0; k < 4; k++) {
            hh[k] = __float2bfloat16(v[k]);
            ll[k] = __float2bfloat16(v[k] - __bfloat162float(hh[k]));
        }
        __nv_bfloat162 p0, p1, q0, q1;
        p0.x = hh[0]; p0.y = hh[1]; p1.x = hh[2]; p1.y = hh[3];
        q0.x = ll[0]; q0.y = ll[1]; q1.x = ll[2]; q1.y = ll[3];
        *(__nv_bfloat162*)(Xh + base + i)     = p0;
        *(__nv_bfloat162*)(Xh + base + i + 2) = p1;
        *(__nv_bfloat162*)(Xl + base + i)     = q0;
        *(__nv_bfloat162*)(Xl + base + i + 2) = q1;
    }
}

// ---------------- N-split gemm: 2 CTAs/chunk (channel halves), 2 CTAs/SM ------------
// 128 threads, 4 warps (2x2), warp tile 32(M) x 64(N-local). CTA h owns output
// channels [h*64, h*64+64): stages W0/W1 cols of that range (128 local n-rows).
// One-pass epilogue: C[64][136] overlays the consumed A region; mix + stats.
__global__ __launch_bounds__(128) void sg_gemm_pipe(
    const __nv_bfloat16* __restrict__ Xh, const __nv_bfloat16* __restrict__ Xl,
    const __nv_bfloat16* __restrict__ Wbf, const float* __restrict__ bias,
    int attSlot, int slotOut, int tpc, float* __restrict__ Hout)
{
    extern __shared__ char dsm[];
    __shared__ float att2[256];
    __shared__ float dS[16];
    __shared__ float bS[64];
    __shared__ float sSum[64], sSq[64];

    int tid = threadIdx.x, wid = tid >> 5, lane = tid & 31;
    int wm = wid >> 1, wn = wid & 1;   // 2x2 warp grid, warp tile 32(M) x 64(Nloc)
    int h  = blockIdx.x & 1;           // channel half
    int cg = blockIdx.x >> 1;
    int chunk0 = cg * tpc;
    int set = chunk0 >> 11;
    uint32_t sbase = smem_u32(dsm);

    // ---- stage W half (hi+lo): local wrow -> global n = (wrow>>6)*128 + h*64 + (wrow&63)
    {
        const char* wsrc = (const char*)Wbf;
        #pragma unroll
        for (int j = 0; j < 32; j++) {
            int idx = tid + j*128;             // 4096 pieces
            int kind = idx >> 11, rem = idx & 2047;
            int wrow = rem >> 4, p = rem & 15;
            int n = ((wrow >> 6)*128) + h*64 + (wrow & 63);
            uint32_t dst = sbase + OFF_WH + kind*WBUF + wrow*ROWP + p*16;
            CP_ASYNC16(dst, wsrc + kind*65536 + n*256 + p*16);
        }
        long row0 = (long)chunk0 * 64;
        #pragma unroll
        for (int j = 0; j < 16; j++) {
            int idx = tid + j*128;             // 2048 A pieces
            int kind = idx >> 10, rem = idx & 1023;
            int r = rem >> 4, p = rem & 15;
            const char* src = (const char*)(kind ? Xl : Xh) + (row0 + r)*256 + p*16;
            uint32_t dst = sbase + OFF_AH + kind*ABUF + r*ROWP + p*16;
            CP_ASYNC16(dst, src);
        }
        CP_COMMIT();
    }

    if (tid < 64) { bS[tid] = bias[h*64 + tid]; sSum[tid] = 0.f; sSq[tid] = 0.f; }
    for (int q = tid; q < 256; q += 128) {
        float av = g_att[attSlot*256 + q];
        int i = q >> 4, j = q & 15;
        att2[q] = (i == j) ? 0.f : av;
        if (i == j) dS[i] = av;
    }

    // ldmatrix lane addressing
    int sub = lane >> 3, lr = lane & 7;
    int arow = wm*32 + (sub & 1)*8 + lr;
    uint32_t aOffRow = arow*ROWP + (sub >> 1)*16;
    int brow = wn*64 + ((lane >> 4) & 1)*8 + lr;   // local W rows 0..127
    int bkh  = (lane >> 3) & 1;
    uint32_t bAddrH = sbase + OFF_WH + brow*ROWP + bkh*16;
    uint32_t bAddrL = sbase + OFF_WL + brow*ROWP + bkh*16;
    int g = lane >> 2, tg = lane & 3;

    for (int tt = 0; tt < tpc; tt++) {
        long row0 = (long)(chunk0 + tt) * 64;
        uint32_t aH = sbase + OFF_AH + aOffRow;
        uint32_t aL = aH + ABUF;

        CP_WAIT0();
        __syncthreads();

        // ---- mainloop: warp tile 32x64 over local 64x128 ----
        float acc[2][8][4];
        #pragma unroll
        for (int mt = 0; mt < 2; mt++)
            #pragma unroll
            for (int nt = 0; nt < 8; nt++)
                #pragma unroll
                for (int q = 0; q < 4; q++) acc[mt][nt][q] = 0.f;

        #pragma unroll
        for (int ks = 0; ks < 8; ks++) {
            uint32_t ah[2][4], al[2][4];
            ldsm4(ah[0], aH + ks*32);
            ldsm4(ah[1], aH + ks*32 + 16*ROWP);
            ldsm4(al[0], aL + ks*32);
            ldsm4(al[1], aL + ks*32 + 16*ROWP);
            #pragma unroll
            for (int pr = 0; pr < 4; pr++) {
                uint32_t bh[4], bl[4];
                ldsm4(bh, bAddrH + ks*32 + pr*16*ROWP);
                ldsm4(bl, bAddrL + ks*32 + pr*16*ROWP);
                #pragma unroll
                for (int hf = 0; hf < 2; hf++) {
                    int nt = pr*2 + hf;
                    #pragma unroll
                    for (int mt = 0; mt < 2; mt++) {
                        mma16816(acc[mt][nt], ah[mt], bh + hf*2);
                        mma16816(acc[mt][nt], al[mt], bh + hf*2);
                        mma16816(acc[mt][nt], ah[mt], bl + hf*2);
                    }
                }
            }
        }
        __syncthreads();   // A consumed -> reuse region as C[64][CBS]

        // ---- store C (local cols 0..63 = C0 half, 64..127 = C1 half) ----
        float* Cs = (float*)dsm;
        #pragma unroll
        for (int mt = 0; mt < 2; mt++) {
            int rb = wm*32 + mt*16 + g;
            #pragma unroll
            for (int nt = 0; nt < 8; nt++) {
                int lc = wn*64 + nt*8 + tg*2;
                float2 v0; v0.x = acc[mt][nt][0]; v0.y = acc[mt][nt][1];
                float2 v1; v1.x = acc[mt][nt][2]; v1.y = acc[mt][nt][3];
                *(float2*)(Cs + rb*CBS + lc)     = v0;
                *(float2*)(Cs + (rb+8)*CBS + lc) = v1;
            }
        }
        __syncthreads();

        // ---- one-pass mix: 2 tasks/thread (4 samples x 64 channels) ----
        #pragma unroll
        for (int rep = 0; rep < 2; rep++) {
            int si = (tid >> 6) + rep*2;       // sample 0..3
            int c  = tid & 63;
            int ch = h*64 + c;
            float a[16];
            float bb = bS[c];
            #pragma unroll
            for (int i = 0; i < 16; i++)
                a[i] = fmaf(dS[i], Cs[(si*16+i)*CBS + c], bb);
            #pragma unroll
            for (int j = 0; j < 16; j++) {
                float v = Cs[(si*16+j)*CBS + 64 + c];
                #pragma unroll
                for (int i = 0; i < 16; i++)
                    a[i] = fmaf(att2[i*16+j], v, a[i]);
            }
            float cs = 0.f, cq = 0.f;
            #pragma unroll
            for (int i = 0; i < 16; i++) {
                Hout[(row0 + si*16 + i)*128 + ch] = a[i];
                cs += a[i]; cq += a[i]*a[i];
            }
            atomicAdd(&sSum[c], cs);
            atomicAdd(&sSq[c],  cq);
        }
        __syncthreads();

        // ---- prefetch next chunk's A into freed region ----
        if (tt + 1 < tpc) {
            long rowN = (long)(chunk0 + tt + 1) * 64;
            #pragma unroll
            for (int j = 0; j < 16; j++) {
                int idx = tid + j*128;
                int kind = idx >> 10, rem = idx & 1023;
                int r = rem >> 4, p = rem & 15;
                const char* src = (const char*)(kind ? Xl : Xh) + (rowN + r)*256 + p*16;
                uint32_t dst = sbase + OFF_AH + kind*ABUF + r*ROWP + p*16;
                CP_ASYNC16(dst, src);
            }
            CP_COMMIT();
        }
    }
    __syncthreads();
    if (tid < 64) {
        atomicAdd(&g_sum  [slotOut*512 + set*128 + h*64 + tid], (double)sSum[tid]);
        atomicAdd(&g_sumsq[slotOut*512 + set*128 + h*64 + tid], (double)sSq[tid]);
    }
}

// ---------------- output semgconv (128 -> 3), hi/lo input ----------------
__global__ void sg_gconv_out(const __nv_bfloat16* __restrict__ Xh, const __nv_bfloat16* __restrict__ Xl,
                             const float* __restrict__ Wout, const float* __restrict__ bout,
                             int finalMode, float* __restrict__ outp, float* __restrict__ merged)
{
    __shared__ float xs[4*16*129];
    __shared__ float Wl[768];
    __shared__ float attL[256];
    __shared__ float h1s[4][16][3];
    __shared__ float bL[3];
    int t  = threadIdx.x;              // 128
    int s0 = blockIdx.x * 4;
    int branch = finalMode ? 4 : (s0 >> 13);

    for (int i = t; i < 768; i += 128) Wl[i] = Wout[branch*768 + i];
    for (int i = t; i < 256; i += 128) attL[i] = g_att[(10+branch)*256 + i];
    if (t < 3) bL[t] = bout[branch*3 + t];
    for (int i = t; i < 4*16*128; i += 128) {
        int s = i >> 11, rem = i & 2047, j = rem >> 7, k = rem & 127;
        long gi = ((long)(s0+s)*16 + j)*128 + k;
        xs[(s*16+j)*129 + k] = __bfloat162float(Xh[gi]) + __bfloat162float(Xl[gi]);
    }
    __syncthreads();

    int si = t >> 4, ji = t & 15;
    float h0[3] = {0.f,0.f,0.f};
    if (t < 64) {
        float h1[3] = {0.f,0.f,0.f};
        const float* xr = xs + (si*16 + ji)*129;
        for (int k = 0; k < 128; k++) {
            float x = xr[k];
            h0[0] += x*Wl[k*3+0]; h0[1] += x*Wl[k*3+1]; h0[2] += x*Wl[k*3+2];
            h1[0] += x*Wl[384+k*3+0]; h1[1] += x*Wl[384+k*3+1]; h1[2] += x*Wl[384+k*3+2];
        }
        h1s[si][ji][0]=h1[0]; h1s[si][ji][1]=h1[1]; h1s[si][ji][2]=h1[2];
    }
    __syncthreads();
    if (t < 64) {
        float dd = attL[ji*17];
        float o[3];
        #pragma unroll
        for (int c = 0; c < 3; c++) o[c] = dd*h0[c] + bL[c];
        #pragma unroll
        for (int j = 0; j < 16; j++) {
            if (j == ji) continue;
            float a = attL[ji*16 + j];
            o[0] += a*h1s[si][j][0]; o[1] += a*h1s[si][j][1]; o[2] += a*h1s[si][j][2];
        }
        if (finalMode) {
            long row = ((long)(s0+si)*16 + ji)*3;
            outp[row+0]=o[0]; outp[row+1]=o[1]; outp[row+2]=o[2];
        } else {
            int loc = (s0+si) & (BB-1);
            long ob = (long)(1+branch)*BB*48 + ((long)loc*16 + ji)*3;
            outp[ob+0]=o[0]; outp[ob+1]=o[1]; outp[ob+2]=o[2];
            long mb = ((long)loc*16 + ji)*12 + branch*3;
            merged[mb+0]=o[0]; merged[mb+1]=o[1]; merged[mb+2]=o[2];
        }
    }
}

// ---------------- host orchestration ----------------
extern "C" void kernel_launch(void* const* d_in, const int* in_sizes, int n_in,
                              void* d_out, int out_size)
{
    const float* x1       = (const float*)d_in[0];
    const float* x2       = (const float*)d_in[1];
    const float* x3       = (const float*)d_in[2];
    const float* x4       = (const float*)d_in[3];
    const float* W_in     = (const float*)d_in[4];
    const float* b_in     = (const float*)d_in[5];
    const float* e_in     = (const float*)d_in[6];
    const float* g_in     = (const float*)d_in[7];
    const float* beta_in  = (const float*)d_in[8];
    const float* W_cat    = (const float*)d_in[9];
    const float* b_cat    = (const float*)d_in[10];
    const float* e_cat    = (const float*)d_in[11];
    const float* g_cat    = (const float*)d_in[12];
    const float* beta_cat = (const float*)d_in[13];
    const float* W_res    = (const float*)d_in[14];
    const float* b_res    = (const float*)d_in[15];
    const float* e_res    = (const float*)d_in[16];
    const float* g_res    = (const float*)d_in[17];
    const float* beta_res = (const float*)d_in[18];
    const float* W_out    = (const float*)d_in[19];
    const float* b_out    = (const float*)d_in[20];
    const float* e_out    = (const float*)d_in[21];
    float* out = (float*)d_out;

    float *Hb, *Mb;
    __nv_bfloat16 *Xh0, *Xl0, *Xh1, *Xl1, *Wb;
    cudaGetSymbolAddress((void**)&Hb,  g_H);
    cudaGetSymbolAddress((void**)&Mb,  g_merged);
    cudaGetSymbolAddress((void**)&Xh0, g_Xh0);
    cudaGetSymbolAddress((void**)&Xl0, g_Xl0);
    cudaGetSymbolAddress((void**)&Xh1, g_Xh1);
    cudaGetSymbolAddress((void**)&Xl1, g_Xl1);
    cudaGetSymbolAddress((void**)&Wb,  g_Wbf);

    cudaFuncSetAttribute(sg_gemm_pipe, cudaFuncAttributeMaxDynamicSharedMemorySize, GEMM_SMEM);

    sg_prep0<<<1024,256>>>(W_res, e_in, e_cat, e_res, e_out);

    for (int phase = 0; phase < 2; phase++) {
        int nS      = phase ? BB : NS4;
        int nRows   = nS*JJ;
        int nChunks = nRows/64;
        int TPC     = phase ? 2 : 8;
        int sb      = phase*9;
        if (phase == 0)
            sg_gconv_smallk<2><<<nS/8,128>>>(x1,x2,x3,x4, 1, W_in, b_in, 0, sb, Hb);
        else
            sg_gconv_smallk<12><<<nS/8,128>>>(Mb, nullptr, nullptr, nullptr, 0, W_cat, b_cat, 1, sb, Hb);

        const float* gIn0 = phase ? g_cat : g_in;
        const float* bIn0 = phase ? beta_cat : beta_in;
        sg_convert<<<nRows/64,256>>>(Hb, nullptr, nullptr, Xh0, Xl0, gIn0, bIn0, sb);

        for (int s = 0; s < 8; s++) {
            const __nv_bfloat16* Xhi = (s & 1) ? Xh1 : Xh0;
            const __nv_bfloat16* Xli = (s & 1) ? Xl1 : Xl0;
            sg_gemm_pipe<<<(nChunks/TPC)*2, 128, GEMM_SMEM>>>(
                Xhi, Xli, Wb + (long)s*65536, b_res + s*128, 2+s, sb+s+1, TPC, Hb);
            __nv_bfloat16* Xho = (s & 1) ? Xh0 : Xh1;
            __nv_bfloat16* Xlo = (s & 1) ? Xl0 : Xl1;
            const __nv_bfloat16* Rh = (s & 1) ? Xh0 : nullptr;
            const __nv_bfloat16* Rl = (s & 1) ? Xl0 : nullptr;
            sg_convert<<<nRows/64,256>>>(Hb, Rh, Rl, Xho, Xlo,
                                         g_res + s*128, beta_res + s*128, sb+s+1);
        }
        sg_gconv_out<<<nS/4,128>>>(Xh0, Xl0, W_out, b_out, phase, out, phase ? nullptr : Mb);
    }
}